// round 14
// baseline (speedup 1.0000x reference)
#include <cuda_runtime.h>
#include <cstdint>

// EmbedWeighted == out(B,D) = inputs(B,V) @ embeddings(V,D)
// fp16 mma.sync; ALL A preloaded to registers; zero global loads in mainloop.
#define B_DIM 2048
#define V_DIM 2000
#define D_DIM 64
#define NSPLIT 16
#define KSPLIT 128            // uniform k_len=128 (zero-padded beyond 2000)
#define NK 8                  // k16 steps per CTA (uniform)
#define NTHREADS 256
#define MTILE 128
#define NMTILE (B_DIM / MTILE)            // 16
#define ET_STR 68             // words/row: 4 mod 32 -> frag banks (4g+t)%32 distinct

__device__ float g_partials[NSPLIT][B_DIM][D_DIM];   // 8 MB static scratch
__device__ unsigned g_arrive[NMTILE];                // zero-init, self-resetting
__device__ unsigned g_done[NMTILE];

static __device__ __forceinline__ uint32_t smem_u32(const void* p) {
    return (uint32_t)__cvta_generic_to_shared(p);
}
static __device__ __forceinline__ uint32_t lds32(uint32_t a) {
    uint32_t v; asm("ld.shared.b32 %0, [%1];" : "=r"(v) : "r"(a)); return v;
}
static __device__ __forceinline__ uint32_t pack_h2(float lo, float hi) {
    uint32_t r;   // d.hi = cvt(%1), d.lo = cvt(%2)
    asm("cvt.rn.f16x2.f32 %0, %1, %2;" : "=r"(r) : "f"(hi), "f"(lo));
    return r;
}
static __device__ __forceinline__ float2 ldgA2(const float* p) {
    float2 v;   // 8B used, 256B prefetched into L2
    asm("ld.global.nc.L2::256B.v2.f32 {%0,%1}, [%2];"
        : "=f"(v.x), "=f"(v.y) : "l"(p));
    return v;
}
static __device__ __forceinline__ float ldgE(const float* p) {
    float v;
    asm("ld.global.nc.L2::256B.f32 %0, [%1];" : "=f"(v) : "l"(p));
    return v;
}

// 256 threads, 8 warps; warp tile 16m x 64n. CTA tile 128x64.
// grid (16, 16) = 256 CTAs, occ 2 -> all co-resident (capacity 296).
__global__ __launch_bounds__(NTHREADS, 2)
void embedweighted_areg(const float* __restrict__ inp,
                        const float* __restrict__ emb,
                        float* __restrict__ out)
{
    __shared__ __align__(16) uint32_t Et[D_DIM * ET_STR];   // fp16 Et[n][k], 17408 B

    const int ksplit = blockIdx.x;
    const int mtile  = blockIdx.y;
    const int m_base = mtile * MTILE;
    const int k_base = ksplit * KSPLIT;

    const int tid  = threadIdx.x;
    const int warp = tid >> 5;        // 0..7 -> rows m_base + warp*16 ..
    const int lane = tid & 31;
    const int g = lane >> 2;          // 0..7
    const int t = lane & 3;           // 0..3

    // ---- preload ALL A for this warp: 8 k16-steps x 4 float2 (front-batched) ----
    const float* a0p = inp + (size_t)(m_base + warp * 16 + g) * V_DIM + k_base + 2 * t;
    const float* a8p = a0p + 8 * (size_t)V_DIM;
    const float2 fz = make_float2(0.f, 0.f);
    float2 Ab[NK][4];
    #pragma unroll
    for (int ks = 0; ks < NK; ks++) {
        int k0 = k_base + ks * 16 + 2 * t;        // even, pair valid iff k0 < V_DIM
        bool p0 = (k0 < V_DIM);
        bool p1 = (k0 + 8 < V_DIM);
        int off = ks * 16;
        Ab[ks][0] = p0 ? ldgA2(a0p + off)     : fz;
        Ab[ks][1] = p0 ? ldgA2(a8p + off)     : fz;
        Ab[ks][2] = p1 ? ldgA2(a0p + off + 8) : fz;
        Ab[ks][3] = p1 ? ldgA2(a8p + off + 8) : fz;
    }

    // ---- stage E once: Et[n][k] fp16, k zero-filled beyond V_DIM ----
    {
        const int en = tid & 63;      // n
        const int kb = tid >> 6;      // k-block 0..3 (32 k each)
        #pragma unroll
        for (int i = 0; i < 16; i++) {
            int k0 = k_base + kb * 32 + 2 * i;
            float f0 = (k0     < V_DIM) ? ldgE(emb + (size_t)k0 * D_DIM + en)       : 0.f;
            float f1 = (k0 + 1 < V_DIM) ? ldgE(emb + (size_t)(k0 + 1) * D_DIM + en) : 0.f;
            Et[en * ET_STR + kb * 16 + i] = pack_h2(f0, f1);
        }
    }
    __syncthreads();   // the ONLY gemm barrier: Et visible

    float acc[8][4];
    #pragma unroll
    for (int j = 0; j < 8; j++)
        #pragma unroll
        for (int r = 0; r < 4; r++) acc[j][r] = 0.0f;

    // ---- mainloop: ZERO global loads; pure LDS + pack + MMA ----
    const uint32_t eb = smem_u32(Et) + (uint32_t)(g * ET_STR + t) * 4u;
    #pragma unroll
    for (int ks = 0; ks < NK; ks++) {
        const uint32_t a0 = pack_h2(Ab[ks][0].x, Ab[ks][0].y);
        const uint32_t a1 = pack_h2(Ab[ks][1].x, Ab[ks][1].y);
        const uint32_t a2 = pack_h2(Ab[ks][2].x, Ab[ks][2].y);
        const uint32_t a3 = pack_h2(Ab[ks][3].x, Ab[ks][3].y);

        const uint32_t ecur = eb + (uint32_t)(ks * 8) * 4u;
        #pragma unroll
        for (int nt = 0; nt < 8; nt++) {
            uint32_t b0 = lds32(ecur + (uint32_t)(nt * 8 * ET_STR) * 4u);
            uint32_t b1 = lds32(ecur + (uint32_t)(nt * 8 * ET_STR + 4) * 4u);
            asm volatile(
                "mma.sync.aligned.m16n8k16.row.col.f32.f16.f16.f32 "
                "{%0,%1,%2,%3}, {%4,%5,%6,%7}, {%8,%9}, {%0,%1,%2,%3};"
                : "+f"(acc[nt][0]), "+f"(acc[nt][1]),
                  "+f"(acc[nt][2]), "+f"(acc[nt][3])
                : "r"(a0), "r"(a1), "r"(a2), "r"(a3), "r"(b0), "r"(b1));
        }
    }

    // ---- write 16x64 fp32 partial strip per warp ----
    {
        float* pp = &g_partials[ksplit][m_base + warp * 16][0];
        #pragma unroll
        for (int nt = 0; nt < 8; nt++) {
            int n0c = nt * 8 + 2 * t;
            pp[g * D_DIM + n0c]           = acc[nt][0];
            pp[g * D_DIM + n0c + 1]       = acc[nt][1];
            pp[(g + 8) * D_DIM + n0c]     = acc[nt][2];
            pp[(g + 8) * D_DIM + n0c + 1] = acc[nt][3];
        }
    }

    // ---- fused deterministic split-K reduction (all 256 CTAs co-resident) ----
    __syncthreads();
    if (tid == 0) {
        __threadfence();                       // release partial stores
        atomicAdd(&g_arrive[mtile], 1u);
        unsigned v;
        do {
            asm volatile("ld.acquire.gpu.u32 %0, [%1];" : "=r"(v) : "l"(&g_arrive[mtile]));
            if (v >= NSPLIT) break;
            __nanosleep(64);
        } while (true);
    }
    __syncthreads();   // propagate tid0's acquire CTA-wide

    if (tid < 128) {   // this CTA reduces rows [m_base + ksplit*8, +8): 128 float4
        int r = tid >> 4, q = tid & 15;
        int off = (m_base + ksplit * 8 + r) * (D_DIM / 4) + q;
        const float4* p = reinterpret_cast<const float4*>(&g_partials[0][0][0]);
        float4 s = p[off];
        #pragma unroll
        for (int sp = 1; sp < NSPLIT; sp++) {   // fixed order -> deterministic
            float4 v = p[(size_t)sp * (B_DIM * D_DIM / 4) + off];
            s.x += v.x; s.y += v.y; s.z += v.z; s.w += v.w;
        }
        reinterpret_cast<float4*>(out)[off] = s;
    }

    __syncthreads();
    if (tid == 0) {   // reset counters for graph replay
        unsigned d = atomicAdd(&g_done[mtile], 1u);
        if (d == NSPLIT - 1) {
            atomicExch(&g_arrive[mtile], 0u);
            atomicExch(&g_done[mtile], 0u);
        }
    }
}

extern "C" void kernel_launch(void* const* d_in, const int* in_sizes, int n_in,
                              void* d_out, int out_size)
{
    const float* inputs     = (const float*)d_in[0];   // (B, V) fp32
    const float* embeddings = (const float*)d_in[1];   // (V, D) fp32
    float* out = (float*)d_out;                        // (B, D) fp32

    dim3 grid(NSPLIT, NMTILE);   // 256 CTAs, occ 2 -> all co-resident
    embedweighted_areg<<<grid, NTHREADS>>>(inputs, embeddings, out);
}